// round 1
// baseline (speedup 1.0000x reference)
#include <cuda_runtime.h>
#include <math.h>

#define B_  4
#define S_  2048
#define D_  768
#define H_  12
#define HD_ 64
#define N3_ (3*D_)
#define M_  (B_*S_)

// Scratch (allocation-free rule: __device__ globals)
__device__ float g_q[B_*H_*S_*HD_];     // [b,h,s,d]
__device__ float g_k[B_*H_*S_*HD_];
__device__ float g_v[B_*H_*S_*HD_];
__device__ float g_attn[M_*D_];         // [b,s, h*64+d]

// ---------------------------------------------------------------------------
// GEMM 1: qkv = x @ w_qkv + b_qkv, scatter into per-head q/k/v buffers
// 128x128x16 tile, 8x8 microtile, 256 threads
// ---------------------------------------------------------------------------
__global__ __launch_bounds__(256, 2) void gemm_qkv_kernel(
    const float* __restrict__ A, const float* __restrict__ Bw,
    const float* __restrict__ bias)
{
    __shared__ float As[16][132];   // transposed A tile, padded
    __shared__ float Bs[16][128];
    const int K = D_, N = N3_;
    int tid = threadIdx.x;
    int bx = blockIdx.x, by = blockIdx.y;
    int arow = tid >> 2, acol = (tid & 3) << 2;     // A: 64 rows x 16 cols per half
    int brow = tid >> 5, bcol = (tid & 31) << 2;    // B: 8 rows x 128 cols per half
    int tr = tid >> 4, tc = tid & 15;

    float acc[8][8];
    #pragma unroll
    for (int i = 0; i < 8; i++)
        #pragma unroll
        for (int j = 0; j < 8; j++) acc[i][j] = 0.f;

    const float* Ap = A + (size_t)(by * 128) * K;
    const float* Bp = Bw + bx * 128;

    for (int k0 = 0; k0 < K; k0 += 16) {
        float4 a0 = *(const float4*)(Ap + (size_t)arow * K + k0 + acol);
        float4 a1 = *(const float4*)(Ap + (size_t)(arow + 64) * K + k0 + acol);
        As[acol+0][arow]    = a0.x; As[acol+1][arow]    = a0.y;
        As[acol+2][arow]    = a0.z; As[acol+3][arow]    = a0.w;
        As[acol+0][arow+64] = a1.x; As[acol+1][arow+64] = a1.y;
        As[acol+2][arow+64] = a1.z; As[acol+3][arow+64] = a1.w;
        *(float4*)&Bs[brow][bcol]     = *(const float4*)(Bp + (size_t)(k0 + brow) * N + bcol);
        *(float4*)&Bs[brow + 8][bcol] = *(const float4*)(Bp + (size_t)(k0 + brow + 8) * N + bcol);
        __syncthreads();
        #pragma unroll
        for (int kk = 0; kk < 16; kk++) {
            float ar[8], br[8];
            *(float4*)&ar[0] = *(const float4*)&As[kk][tr * 4];
            *(float4*)&ar[4] = *(const float4*)&As[kk][tr * 4 + 64];
            *(float4*)&br[0] = *(const float4*)&Bs[kk][tc * 4];
            *(float4*)&br[4] = *(const float4*)&Bs[kk][tc * 4 + 64];
            #pragma unroll
            for (int i = 0; i < 8; i++)
                #pragma unroll
                for (int j = 0; j < 8; j++)
                    acc[i][j] += ar[i] * br[j];
        }
        __syncthreads();
    }

    // Epilogue: bias + scatter to [b,h,s,d] layouts
    #pragma unroll
    for (int qi = 0; qi < 2; qi++)
        #pragma unroll
        for (int i = 0; i < 4; i++) {
            int m  = by * 128 + qi * 64 + tr * 4 + i;
            int bb = m >> 11;             // /2048
            int ss = m & (S_ - 1);
            #pragma unroll
            for (int ci = 0; ci < 2; ci++) {
                int n     = bx * 128 + ci * 64 + tc * 4;
                int which = n / D_;
                int rem   = n - which * D_;
                int hh    = rem >> 6;
                int dd    = rem & 63;
                float4 v;
                v.x = acc[qi*4+i][ci*4+0] + bias[n+0];
                v.y = acc[qi*4+i][ci*4+1] + bias[n+1];
                v.z = acc[qi*4+i][ci*4+2] + bias[n+2];
                v.w = acc[qi*4+i][ci*4+3] + bias[n+3];
                float* dst = (which == 0) ? g_q : ((which == 1) ? g_k : g_v);
                *(float4*)&dst[(((size_t)(bb * H_ + hh) * S_ + ss) << 6) + dd] = v;
            }
        }
}

// ---------------------------------------------------------------------------
// Flash attention, causal. One block = one (b, h, 64-row q tile). 256 threads.
// Dynamic SMEM: Qs[64][68](T), Ks[64][68](T), Ps[64][68], Vs[64][64]
// ---------------------------------------------------------------------------
__global__ __launch_bounds__(256) void flash_attn_kernel()
{
    extern __shared__ float sm[];
    float* Qs = sm;                  // [d][q], stride 68 (scaled by attn_scale)
    float* Ks = sm + 64 * 68;        // [d][k], stride 68
    float* Ps = sm + 2 * 64 * 68;    // [q][k], stride 68
    float* Vs = sm + 3 * 64 * 68;    // [k][d], stride 64

    int bid = blockIdx.x;
    int qt  = bid & 31;
    int h   = (bid >> 5) % H_;
    int b   = bid / (32 * H_);
    int tid = threadIdx.x;
    int ty  = tid >> 4, tx = tid & 15;
    int q0  = qt * 64;
    const float scale = 0.125f;      // 1/sqrt(64)

    const float* Qg = g_q + ((size_t)(b * H_ + h) * S_) * HD_;
    const float* Kg = g_k + ((size_t)(b * H_ + h) * S_) * HD_;
    const float* Vg = g_v + ((size_t)(b * H_ + h) * S_) * HD_;

    // Load + transpose Q tile (scale folded in)
    {
        int r = tid >> 4, d0 = (tid & 15) * 4;
        #pragma unroll
        for (int it = 0; it < 4; it++) {
            int rr = r + it * 16;
            float4 qv = *(const float4*)(Qg + (size_t)(q0 + rr) * 64 + d0);
            Qs[(d0+0)*68 + rr] = qv.x * scale;
            Qs[(d0+1)*68 + rr] = qv.y * scale;
            Qs[(d0+2)*68 + rr] = qv.z * scale;
            Qs[(d0+3)*68 + rr] = qv.w * scale;
        }
    }

    float m_i[4], l_i[4], o[4][4];
    #pragma unroll
    for (int i = 0; i < 4; i++) {
        m_i[i] = -INFINITY; l_i[i] = 0.f;
        #pragma unroll
        for (int j = 0; j < 4; j++) o[i][j] = 0.f;
    }

    for (int kt = 0; kt <= qt; kt++) {
        int k0 = kt * 64;
        // Load K (transposed) and V
        {
            int r = tid >> 4, d0 = (tid & 15) * 4;
            #pragma unroll
            for (int it = 0; it < 4; it++) {
                int rr = r + it * 16;
                float4 kv = *(const float4*)(Kg + (size_t)(k0 + rr) * 64 + d0);
                Ks[(d0+0)*68 + rr] = kv.x; Ks[(d0+1)*68 + rr] = kv.y;
                Ks[(d0+2)*68 + rr] = kv.z; Ks[(d0+3)*68 + rr] = kv.w;
                *(float4*)&Vs[rr * 64 + d0] = *(const float4*)(Vg + (size_t)(k0 + rr) * 64 + d0);
            }
        }
        __syncthreads();

        // S = (Q*scale) @ K^T
        float s[4][4];
        #pragma unroll
        for (int i = 0; i < 4; i++)
            #pragma unroll
            for (int j = 0; j < 4; j++) s[i][j] = 0.f;
        #pragma unroll 8
        for (int d = 0; d < 64; d++) {
            float4 qv = *(const float4*)&Qs[d * 68 + ty * 4];
            float4 kv = *(const float4*)&Ks[d * 68 + tx * 4];
            float qa[4] = {qv.x, qv.y, qv.z, qv.w};
            float ka[4] = {kv.x, kv.y, kv.z, kv.w};
            #pragma unroll
            for (int i = 0; i < 4; i++)
                #pragma unroll
                for (int j = 0; j < 4; j++)
                    s[i][j] += qa[i] * ka[j];
        }

        if (kt == qt) {  // diagonal tile: causal mask
            #pragma unroll
            for (int i = 0; i < 4; i++)
                #pragma unroll
                for (int j = 0; j < 4; j++)
                    if (4 * tx + j > 4 * ty + i) s[i][j] = -INFINITY;
        }

        // Online softmax update (rows owned by 16-lane groups)
        #pragma unroll
        for (int i = 0; i < 4; i++) {
            float mt = fmaxf(fmaxf(s[i][0], s[i][1]), fmaxf(s[i][2], s[i][3]));
            #pragma unroll
            for (int off = 8; off; off >>= 1)
                mt = fmaxf(mt, __shfl_xor_sync(0xffffffffu, mt, off, 16));
            float mnew  = fmaxf(m_i[i], mt);
            float alpha = __expf(m_i[i] - mnew);
            float rs = 0.f;
            #pragma unroll
            for (int j = 0; j < 4; j++) {
                s[i][j] = __expf(s[i][j] - mnew);
                rs += s[i][j];
            }
            #pragma unroll
            for (int off = 8; off; off >>= 1)
                rs += __shfl_xor_sync(0xffffffffu, rs, off, 16);
            l_i[i] = l_i[i] * alpha + rs;
            m_i[i] = mnew;
            #pragma unroll
            for (int j = 0; j < 4; j++) o[i][j] *= alpha;
            *(float4*)&Ps[(4 * ty + i) * 68 + 4 * tx] =
                make_float4(s[i][0], s[i][1], s[i][2], s[i][3]);
        }
        __syncthreads();

        // O += P @ V
        #pragma unroll 8
        for (int kk = 0; kk < 64; kk++) {
            float4 vv = *(const float4*)&Vs[kk * 64 + tx * 4];
            float va[4] = {vv.x, vv.y, vv.z, vv.w};
            float pv[4];
            #pragma unroll
            for (int i = 0; i < 4; i++) pv[i] = Ps[(4 * ty + i) * 68 + kk];
            #pragma unroll
            for (int i = 0; i < 4; i++)
                #pragma unroll
                for (int j = 0; j < 4; j++)
                    o[i][j] += pv[i] * va[j];
        }
        __syncthreads();
    }

    // Normalize and write to [b, s, h*64+d]
    #pragma unroll
    for (int i = 0; i < 4; i++) {
        float inv = 1.f / l_i[i];
        int srow = q0 + 4 * ty + i;
        float4 v = make_float4(o[i][0]*inv, o[i][1]*inv, o[i][2]*inv, o[i][3]*inv);
        *(float4*)&g_attn[((size_t)(b * S_ + srow)) * D_ + h * 64 + 4 * tx] = v;
    }
}

// ---------------------------------------------------------------------------
// GEMM 2: out = attn @ w_proj + b_proj
// ---------------------------------------------------------------------------
__global__ __launch_bounds__(256, 2) void gemm_proj_kernel(
    const float* __restrict__ Bw, const float* __restrict__ bias,
    float* __restrict__ C)
{
    __shared__ float As[16][132];
    __shared__ float Bs[16][128];
    const int K = D_, N = D_;
    int tid = threadIdx.x;
    int bx = blockIdx.x, by = blockIdx.y;
    int arow = tid >> 2, acol = (tid & 3) << 2;
    int brow = tid >> 5, bcol = (tid & 31) << 2;
    int tr = tid >> 4, tc = tid & 15;

    float acc[8][8];
    #pragma unroll
    for (int i = 0; i < 8; i++)
        #pragma unroll
        for (int j = 0; j < 8; j++) acc[i][j] = 0.f;

    const float* Ap = g_attn + (size_t)(by * 128) * K;
    const float* Bp = Bw + bx * 128;

    for (int k0 = 0; k0 < K; k0 += 16) {
        float4 a0 = *(const float4*)(Ap + (size_t)arow * K + k0 + acol);
        float4 a1 = *(const float4*)(Ap + (size_t)(arow + 64) * K + k0 + acol);
        As[acol+0][arow]    = a0.x; As[acol+1][arow]    = a0.y;
        As[acol+2][arow]    = a0.z; As[acol+3][arow]    = a0.w;
        As[acol+0][arow+64] = a1.x; As[acol+1][arow+64] = a1.y;
        As[acol+2][arow+64] = a1.z; As[acol+3][arow+64] = a1.w;
        *(float4*)&Bs[brow][bcol]     = *(const float4*)(Bp + (size_t)(k0 + brow) * N + bcol);
        *(float4*)&Bs[brow + 8][bcol] = *(const float4*)(Bp + (size_t)(k0 + brow + 8) * N + bcol);
        __syncthreads();
        #pragma unroll
        for (int kk = 0; kk < 16; kk++) {
            float ar[8], br[8];
            *(float4*)&ar[0] = *(const float4*)&As[kk][tr * 4];
            *(float4*)&ar[4] = *(const float4*)&As[kk][tr * 4 + 64];
            *(float4*)&br[0] = *(const float4*)&Bs[kk][tc * 4];
            *(float4*)&br[4] = *(const float4*)&Bs[kk][tc * 4 + 64];
            #pragma unroll
            for (int i = 0; i < 8; i++)
                #pragma unroll
                for (int j = 0; j < 8; j++)
                    acc[i][j] += ar[i] * br[j];
        }
        __syncthreads();
    }

    #pragma unroll
    for (int qi = 0; qi < 2; qi++)
        #pragma unroll
        for (int i = 0; i < 4; i++) {
            int m = by * 128 + qi * 64 + tr * 4 + i;
            #pragma unroll
            for (int ci = 0; ci < 2; ci++) {
                int n = bx * 128 + ci * 64 + tc * 4;
                float4 v;
                v.x = acc[qi*4+i][ci*4+0] + bias[n+0];
                v.y = acc[qi*4+i][ci*4+1] + bias[n+1];
                v.z = acc[qi*4+i][ci*4+2] + bias[n+2];
                v.w = acc[qi*4+i][ci*4+3] + bias[n+3];
                *(float4*)&C[(size_t)m * N + n] = v;
            }
        }
}

// ---------------------------------------------------------------------------
extern "C" void kernel_launch(void* const* d_in, const int* in_sizes, int n_in,
                              void* d_out, int out_size)
{
    const float* x      = (const float*)d_in[0];
    const float* w_qkv  = (const float*)d_in[1];
    const float* b_qkv  = (const float*)d_in[2];
    const float* w_proj = (const float*)d_in[3];
    const float* b_proj = (const float*)d_in[4];
    float* out = (float*)d_out;

    dim3 g1(N3_ / 128, M_ / 128);   // (18, 64)
    gemm_qkv_kernel<<<g1, 256>>>(x, w_qkv, b_qkv);

    int smem = (3 * 64 * 68 + 64 * 64) * (int)sizeof(float);   // 68608 B
    cudaFuncSetAttribute(flash_attn_kernel,
                         cudaFuncAttributeMaxDynamicSharedMemorySize, smem);
    flash_attn_kernel<<<B_ * H_ * (S_ / 64), 256, smem>>>();

    dim3 g2(D_ / 128, M_ / 128);    // (6, 64)
    gemm_proj_kernel<<<g2, 256>>>(w_proj, b_proj, out);
}

// round 3
// speedup vs baseline: 1.7980x; 1.7980x over previous
#include <cuda_runtime.h>
#include <math.h>
#include <stdint.h>

#define B_  4
#define S_  2048
#define D_  768
#define H_  12
#define HD_ 64
#define N3_ (3*D_)
#define M_  (B_*S_)

// Scratch (allocation-free rule: __device__ globals)
__device__ float g_q[B_*H_*S_*HD_];     // [b,h,s,d]
__device__ float g_k[B_*H_*S_*HD_];
__device__ float g_v[B_*H_*S_*HD_];
__device__ float g_attn[M_*D_];         // [b,s, h*64+d]

// ---------------------------------------------------------------------------
// tf32 helpers
// ---------------------------------------------------------------------------
__device__ __forceinline__ float tf32r(float x) {
    uint32_t u;
    asm("cvt.rna.tf32.f32 %0, %1;" : "=r"(u) : "f"(x));
    return __uint_as_float(u);
}

__device__ __forceinline__ void mma8(float c[4], const uint32_t a[4], const uint32_t b[2]) {
    asm volatile(
        "mma.sync.aligned.m16n8k8.row.col.f32.tf32.tf32.f32 "
        "{%0,%1,%2,%3},{%4,%5,%6,%7},{%8,%9},{%0,%1,%2,%3};"
        : "+f"(c[0]), "+f"(c[1]), "+f"(c[2]), "+f"(c[3])
        : "r"(a[0]), "r"(a[1]), "r"(a[2]), "r"(a[3]), "r"(b[0]), "r"(b[1]));
}

__device__ __forceinline__ uint32_t fbits(float x) { return __float_as_uint(x); }

// ---------------------------------------------------------------------------
// tf32 GEMM: C[M x N] = A[M x 768] @ W[768 x N] + bias
// CTA 128x128x32, 256 threads, 8 warps in 4x2, warp tile 32x64.
// QKV=true: A = arg, scatter into g_q/g_k/g_v.
// QKV=false: A = g_attn (device symbol, referenced in device code only!),
//            writes C row-major with bias.
// ---------------------------------------------------------------------------
template<bool QKV>
__global__ __launch_bounds__(256, 1) void gemm_tf32(
    const float* __restrict__ A, const float* __restrict__ Bw,
    const float* __restrict__ bias, float* __restrict__ C, int N)
{
    __shared__ float As[32][136];   // [k][m], tf32-rounded
    __shared__ float Bs[32][136];   // [k][n], tf32-rounded
    const int K = D_;

    int tid = threadIdx.x, bx = blockIdx.x, by = blockIdx.y;
    int lane = tid & 31, wid = tid >> 5, lg = lane >> 2, lq = lane & 3;
    int wm = (wid >> 1) * 32, wn = (wid & 1) * 64;

    int arow = tid >> 1, acol0 = (tid & 1) * 16;
    int brow = tid >> 3, bc = tid & 7;

    const float* Abase = QKV ? A : (const float*)g_attn;   // device-side symbol ref
    const float* Ag = Abase + (size_t)(by * 128 + arow) * K + acol0;
    const float* Bg = Bw + (size_t)brow * N + bx * 128 + bc * 4;

    float4 pa[4], pb[4];
    #pragma unroll
    for (int j = 0; j < 4; j++) pa[j] = *(const float4*)(Ag + j * 4);
    #pragma unroll
    for (int j = 0; j < 4; j++) pb[j] = *(const float4*)(Bg + j * 32);

    float acc[2][8][4];
    #pragma unroll
    for (int mt = 0; mt < 2; mt++)
        #pragma unroll
        for (int nt = 0; nt < 8; nt++)
            #pragma unroll
            for (int i = 0; i < 4; i++) acc[mt][nt][i] = 0.f;

    for (int it = 0; it < 24; it++) {
        __syncthreads();
        // Store prefetched tiles to SMEM with tf32 rounding
        #pragma unroll
        for (int j = 0; j < 4; j++) {
            As[acol0 + j*4 + 0][arow] = tf32r(pa[j].x);
            As[acol0 + j*4 + 1][arow] = tf32r(pa[j].y);
            As[acol0 + j*4 + 2][arow] = tf32r(pa[j].z);
            As[acol0 + j*4 + 3][arow] = tf32r(pa[j].w);
        }
        #pragma unroll
        for (int j = 0; j < 4; j++) {
            float4 t;
            t.x = tf32r(pb[j].x); t.y = tf32r(pb[j].y);
            t.z = tf32r(pb[j].z); t.w = tf32r(pb[j].w);
            *(float4*)&Bs[brow][(bc + j*8) * 4] = t;
        }
        __syncthreads();

        if (it < 23) {
            const float* Ag2 = Ag + (it + 1) * 32;
            #pragma unroll
            for (int j = 0; j < 4; j++) pa[j] = *(const float4*)(Ag2 + j * 4);
            const float* Bg2 = Bg + (size_t)(it + 1) * 32 * N;
            #pragma unroll
            for (int j = 0; j < 4; j++) pb[j] = *(const float4*)(Bg2 + j * 32);
        }

        #pragma unroll
        for (int kk = 0; kk < 4; kk++) {
            int kr = kk * 8;
            uint32_t af[2][4], bf[8][2];
            #pragma unroll
            for (int mt = 0; mt < 2; mt++) {
                af[mt][0] = fbits(As[kr + lq    ][wm + mt*16 + lg    ]);
                af[mt][1] = fbits(As[kr + lq    ][wm + mt*16 + lg + 8]);
                af[mt][2] = fbits(As[kr + lq + 4][wm + mt*16 + lg    ]);
                af[mt][3] = fbits(As[kr + lq + 4][wm + mt*16 + lg + 8]);
            }
            #pragma unroll
            for (int nt = 0; nt < 8; nt++) {
                bf[nt][0] = fbits(Bs[kr + lq    ][wn + nt*8 + lg]);
                bf[nt][1] = fbits(Bs[kr + lq + 4][wn + nt*8 + lg]);
            }
            #pragma unroll
            for (int mt = 0; mt < 2; mt++)
                #pragma unroll
                for (int nt = 0; nt < 8; nt++)
                    mma8(acc[mt][nt], af[mt], bf[nt]);
        }
    }

    // Epilogue
    #pragma unroll
    for (int mt = 0; mt < 2; mt++) {
        #pragma unroll
        for (int rp = 0; rp < 2; rp++) {
            int m = by * 128 + wm + mt * 16 + lg + rp * 8;
            if (QKV) {
                int bb = m >> 11;
                int ss = m & (S_ - 1);
                #pragma unroll
                for (int nt = 0; nt < 8; nt++) {
                    int n = bx * 128 + wn + nt * 8 + 2 * lq;
                    int which = n / D_;
                    int rem = n - which * D_;
                    int hh = rem >> 6, dd = rem & 63;
                    float2 v;
                    v.x = acc[mt][nt][rp*2 + 0] + bias[n];
                    v.y = acc[mt][nt][rp*2 + 1] + bias[n + 1];
                    float* dst = (which == 0) ? g_q : ((which == 1) ? g_k : g_v);
                    *(float2*)&dst[(((size_t)(bb * H_ + hh) * S_ + ss) << 6) + dd] = v;
                }
            } else {
                #pragma unroll
                for (int nt = 0; nt < 8; nt++) {
                    int n = bx * 128 + wn + nt * 8 + 2 * lq;
                    float2 v;
                    v.x = acc[mt][nt][rp*2 + 0] + bias[n];
                    v.y = acc[mt][nt][rp*2 + 1] + bias[n + 1];
                    *(float2*)&C[(size_t)m * D_ + n] = v;
                }
            }
        }
    }
}

// ---------------------------------------------------------------------------
// Flash attention, causal, tf32 tensor-core. One block = (b, h, 64-row q tile).
// 128 threads (4 warps); warp w owns q rows [w*16, w*16+16).
// Dynamic SMEM: Ks[64][68], Vs[64][68], Ps[64][68] (Ps doubles as Q staging).
// ---------------------------------------------------------------------------
__global__ __launch_bounds__(128) void flash_attn_tf32()
{
    extern __shared__ float sm[];
    float* Ks = sm;                 // [s_k][d] tf32
    float* Vs = sm + 64 * 68;       // [s_k][d] tf32
    float* Ps = sm + 2 * 64 * 68;   // staging: Q tile, then per-warp P tiles

    int bid = blockIdx.x;
    int qt = bid & 31;
    int h  = (bid >> 5) % H_;
    int b  = bid / (32 * H_);
    int tid = threadIdx.x;
    int lane = tid & 31, w = tid >> 5, lg = lane >> 2, lq = lane & 3;
    int q0 = qt * 64;
    const float scale = 0.125f;   // 1/sqrt(64)

    const float* Qg = g_q + (size_t)(b * H_ + h) * S_ * HD_;
    const float* Kg = g_k + (size_t)(b * H_ + h) * S_ * HD_;
    const float* Vg = g_v + (size_t)(b * H_ + h) * S_ * HD_;

    // Stage Q tile (scaled + tf32-rounded) into Ps, then load A-fragments
    {
        int r = tid >> 1, c0 = (tid & 1) * 32;
        #pragma unroll
        for (int j = 0; j < 8; j++) {
            float4 q4 = *(const float4*)(Qg + (size_t)(q0 + r) * 64 + c0 + j * 4);
            float4 t;
            t.x = tf32r(q4.x * scale); t.y = tf32r(q4.y * scale);
            t.z = tf32r(q4.z * scale); t.w = tf32r(q4.w * scale);
            *(float4*)&Ps[r * 68 + c0 + j * 4] = t;
        }
    }
    __syncthreads();

    uint32_t qf[8][4];
    #pragma unroll
    for (int kk = 0; kk < 8; kk++) {
        qf[kk][0] = fbits(Ps[(w*16 + lg    ) * 68 + kk*8 + lq    ]);
        qf[kk][1] = fbits(Ps[(w*16 + lg + 8) * 68 + kk*8 + lq    ]);
        qf[kk][2] = fbits(Ps[(w*16 + lg    ) * 68 + kk*8 + lq + 4]);
        qf[kk][3] = fbits(Ps[(w*16 + lg + 8) * 68 + kk*8 + lq + 4]);
    }

    float mrow[2] = {-INFINITY, -INFINITY};
    float lrow[2] = {0.f, 0.f};
    float o[8][4];
    #pragma unroll
    for (int nt = 0; nt < 8; nt++)
        #pragma unroll
        for (int i = 0; i < 4; i++) o[nt][i] = 0.f;

    for (int kt = 0; kt <= qt; kt++) {
        int k0 = kt * 64;
        __syncthreads();   // prior use of Ks/Vs done
        {
            int r = tid >> 1, c0 = (tid & 1) * 32;
            #pragma unroll
            for (int j = 0; j < 8; j++) {
                float4 k4 = *(const float4*)(Kg + (size_t)(k0 + r) * 64 + c0 + j * 4);
                float4 tk;
                tk.x = tf32r(k4.x); tk.y = tf32r(k4.y);
                tk.z = tf32r(k4.z); tk.w = tf32r(k4.w);
                *(float4*)&Ks[r * 68 + c0 + j * 4] = tk;
                float4 v4 = *(const float4*)(Vg + (size_t)(k0 + r) * 64 + c0 + j * 4);
                float4 tv;
                tv.x = tf32r(v4.x); tv.y = tf32r(v4.y);
                tv.z = tf32r(v4.z); tv.w = tf32r(v4.w);
                *(float4*)&Vs[r * 68 + c0 + j * 4] = tv;
            }
        }
        __syncthreads();

        // S = (Q*scale) @ K^T    (per warp: 16 x 64)
        float s[8][4];
        #pragma unroll
        for (int nt = 0; nt < 8; nt++)
            #pragma unroll
            for (int i = 0; i < 4; i++) s[nt][i] = 0.f;

        #pragma unroll
        for (int nt = 0; nt < 8; nt++) {
            #pragma unroll
            for (int kk = 0; kk < 8; kk++) {
                uint32_t bv[2];
                bv[0] = fbits(Ks[(nt*8 + lg) * 68 + kk*8 + lq    ]);
                bv[1] = fbits(Ks[(nt*8 + lg) * 68 + kk*8 + lq + 4]);
                mma8(s[nt], qf[kk], bv);
            }
        }

        if (kt == qt) {   // diagonal tile: causal mask (q0 == k0, local compare)
            #pragma unroll
            for (int nt = 0; nt < 8; nt++)
                #pragma unroll
                for (int rp = 0; rp < 2; rp++)
                    #pragma unroll
                    for (int j = 0; j < 2; j++) {
                        int col = nt*8 + 2*lq + j;
                        int row = w*16 + lg + rp*8;
                        if (col > row) s[nt][rp*2 + j] = -INFINITY;
                    }
        }

        // Online softmax per row (each thread owns 2 rows: lg, lg+8)
        #pragma unroll
        for (int rp = 0; rp < 2; rp++) {
            float mt = -INFINITY;
            #pragma unroll
            for (int nt = 0; nt < 8; nt++)
                mt = fmaxf(mt, fmaxf(s[nt][rp*2], s[nt][rp*2 + 1]));
            mt = fmaxf(mt, __shfl_xor_sync(0xffffffffu, mt, 1));
            mt = fmaxf(mt, __shfl_xor_sync(0xffffffffu, mt, 2));
            float mnew = fmaxf(mrow[rp], mt);
            float alpha = __expf(mrow[rp] - mnew);
            float rs = 0.f;
            #pragma unroll
            for (int nt = 0; nt < 8; nt++) {
                float e0 = __expf(s[nt][rp*2]     - mnew);
                float e1 = __expf(s[nt][rp*2 + 1] - mnew);
                s[nt][rp*2] = e0; s[nt][rp*2 + 1] = e1;
                rs += e0 + e1;
            }
            rs += __shfl_xor_sync(0xffffffffu, rs, 1);
            rs += __shfl_xor_sync(0xffffffffu, rs, 2);
            lrow[rp] = lrow[rp] * alpha + rs;
            mrow[rp] = mnew;
            #pragma unroll
            for (int nt = 0; nt < 8; nt++) {
                o[nt][rp*2]     *= alpha;
                o[nt][rp*2 + 1] *= alpha;
            }
            // P -> per-warp SMEM region (tf32-rounded), C-layout -> row-major
            #pragma unroll
            for (int nt = 0; nt < 8; nt++) {
                float2 pv;
                pv.x = tf32r(s[nt][rp*2]);
                pv.y = tf32r(s[nt][rp*2 + 1]);
                *(float2*)&Ps[(w*16 + lg + rp*8) * 68 + nt*8 + 2*lq] = pv;
            }
        }
        __syncwarp();

        // O += P @ V
        #pragma unroll
        for (int kk = 0; kk < 8; kk++) {
            uint32_t pa[4];
            pa[0] = fbits(Ps[(w*16 + lg    ) * 68 + kk*8 + lq    ]);
            pa[1] = fbits(Ps[(w*16 + lg + 8) * 68 + kk*8 + lq    ]);
            pa[2] = fbits(Ps[(w*16 + lg    ) * 68 + kk*8 + lq + 4]);
            pa[3] = fbits(Ps[(w*16 + lg + 8) * 68 + kk*8 + lq + 4]);
            #pragma unroll
            for (int nt = 0; nt < 8; nt++) {
                uint32_t bv[2];
                bv[0] = fbits(Vs[(kk*8 + lq    ) * 68 + nt*8 + lg]);
                bv[1] = fbits(Vs[(kk*8 + lq + 4) * 68 + nt*8 + lg]);
                mma8(o[nt], pa, bv);
            }
        }
        __syncwarp();
    }

    // Normalize, write to [b, s, h*64+d]
    #pragma unroll
    for (int rp = 0; rp < 2; rp++) {
        float inv = 1.f / lrow[rp];
        int row = q0 + w*16 + lg + rp*8;
        #pragma unroll
        for (int nt = 0; nt < 8; nt++) {
            int d = nt*8 + 2*lq;
            float2 v;
            v.x = o[nt][rp*2]     * inv;
            v.y = o[nt][rp*2 + 1] * inv;
            *(float2*)&g_attn[((size_t)(b * S_ + row)) * D_ + h * 64 + d] = v;
        }
    }
}

// ---------------------------------------------------------------------------
extern "C" void kernel_launch(void* const* d_in, const int* in_sizes, int n_in,
                              void* d_out, int out_size)
{
    const float* x      = (const float*)d_in[0];
    const float* w_qkv  = (const float*)d_in[1];
    const float* b_qkv  = (const float*)d_in[2];
    const float* w_proj = (const float*)d_in[3];
    const float* b_proj = (const float*)d_in[4];
    float* out = (float*)d_out;

    dim3 g1(N3_ / 128, M_ / 128);   // (18, 64)
    gemm_tf32<true><<<g1, 256>>>(x, w_qkv, b_qkv, nullptr, N3_);

    int smem = 3 * 64 * 68 * (int)sizeof(float);   // 52224 B
    cudaFuncSetAttribute(flash_attn_tf32,
                         cudaFuncAttributeMaxDynamicSharedMemorySize, smem);
    flash_attn_tf32<<<B_ * H_ * (S_ / 64), 128, smem>>>();

    dim3 g2(D_ / 128, M_ / 128);    // (6, 64)
    gemm_tf32<false><<<g2, 256>>>(nullptr, w_proj, b_proj, out, D_);
}

// round 4
// speedup vs baseline: 2.2968x; 1.2774x over previous
#include <cuda_runtime.h>
#include <math.h>
#include <stdint.h>

#define B_  4
#define S_  2048
#define D_  768
#define H_  12
#define HD_ 64
#define N3_ (3*D_)
#define M_  (B_*S_)

// Scratch (allocation-free rule: __device__ globals)
__device__ float g_q[B_*H_*S_*HD_];     // [b,h,s,d]  tf32-rounded
__device__ float g_k[B_*H_*S_*HD_];
__device__ float g_v[B_*H_*S_*HD_];
__device__ float g_attn[M_*D_];         // [b,s, h*64+d]  tf32-rounded
__device__ float g_x[M_*D_];            // tf32-rounded x
__device__ float g_wq[D_*N3_];          // tf32-rounded w_qkv
__device__ float g_wp[D_*D_];           // tf32-rounded w_proj

// ---------------------------------------------------------------------------
// helpers
// ---------------------------------------------------------------------------
__device__ __forceinline__ float tf32r(float x) {
    uint32_t u;
    asm("cvt.rna.tf32.f32 %0, %1;" : "=r"(u) : "f"(x));
    return __uint_as_float(u);
}
__device__ __forceinline__ void mma8(float c[4], const uint32_t a[4], const uint32_t b[2]) {
    asm volatile(
        "mma.sync.aligned.m16n8k8.row.col.f32.tf32.tf32.f32 "
        "{%0,%1,%2,%3},{%4,%5,%6,%7},{%8,%9},{%0,%1,%2,%3};"
        : "+f"(c[0]), "+f"(c[1]), "+f"(c[2]), "+f"(c[3])
        : "r"(a[0]), "r"(a[1]), "r"(a[2]), "r"(a[3]), "r"(b[0]), "r"(b[1]));
}
__device__ __forceinline__ uint32_t fbits(float x) { return __float_as_uint(x); }
__device__ __forceinline__ void cp16(uint32_t sdst, const void* gsrc) {
    asm volatile("cp.async.cg.shared.global [%0], [%1], 16;" :: "r"(sdst), "l"(gsrc));
}
__device__ __forceinline__ void cp_commit() {
    asm volatile("cp.async.commit_group;" ::: "memory");
}
__device__ __forceinline__ uint32_t s2u(const void* p) {
    return (uint32_t)__cvta_generic_to_shared(p);
}

// ---------------------------------------------------------------------------
// Pre-round inputs to tf32 bit patterns (enables cvt-free cp.async GEMMs)
// blockIdx.y selects tensor.
// ---------------------------------------------------------------------------
__global__ void pre_round(const float* __restrict__ x,
                          const float* __restrict__ wq,
                          const float* __restrict__ wp)
{
    int y = blockIdx.y;
    const float4* src; float4* dst; int n4;
    if (y == 0)      { src = (const float4*)x;  dst = (float4*)g_x;  n4 = (M_*D_)/4;   }
    else if (y == 1) { src = (const float4*)wq; dst = (float4*)g_wq; n4 = (D_*N3_)/4;  }
    else             { src = (const float4*)wp; dst = (float4*)g_wp; n4 = (D_*D_)/4;   }
    for (int i = blockIdx.x * blockDim.x + threadIdx.x; i < n4;
         i += gridDim.x * blockDim.x) {
        float4 v = src[i];
        v.x = tf32r(v.x); v.y = tf32r(v.y); v.z = tf32r(v.z); v.w = tf32r(v.w);
        dst[i] = v;
    }
}

// ---------------------------------------------------------------------------
// tf32 GEMM, cp.async 2-stage: C[M x N] = A[M x 768] @ W[768 x N] + bias
// CTA 128x128x32, 256 threads, 8 warps (4x2), warp tile 32x64, 2 CTAs/SM.
// SMEM: As [128][36] ([m][k], pad 4), Bs [32][136] ([k][n], pad 8), x2 stages.
// QKV=true: A=g_x, W=g_wq, scatter tf32-rounded into g_q/g_k/g_v.
// QKV=false: A=g_attn, W=g_wp, write C (+bias) fp32.
// ---------------------------------------------------------------------------
#define AP 36
#define BP 136
#define ASTF (128*AP)              // 4608 floats
#define BSTF (32*BP)               // 4352 floats
#define STG  (ASTF + BSTF)         // 8960 floats per stage

template<bool QKV>
__global__ __launch_bounds__(256, 2) void gemm_tf32(
    const float* __restrict__ bias, float* __restrict__ C, int N)
{
    extern __shared__ float sm[];
    const int K = D_;
    int tid = threadIdx.x, bx = blockIdx.x, by = blockIdx.y;
    int lane = tid & 31, wid = tid >> 5, lg = lane >> 2, lq = lane & 3;
    int wm = (wid >> 1) * 32, wn = (wid & 1) * 64;

    const float* Abase = QKV ? (const float*)g_x  : (const float*)g_attn;
    const float* Bbase = QKV ? (const float*)g_wq : (const float*)g_wp;

    // cp.async source/dest mapping
    int ar = tid >> 1, ac = (tid & 1) * 16;        // A: row, col-base (4 chunks of 4)
    int br = tid >> 3, bc4 = (tid & 7) * 4;        // B: row, col-base (4 chunks stride 32)
    const float* asrc = Abase + (size_t)(by * 128 + ar) * K + ac;
    const float* bsrc = Bbase + (size_t)br * N + bx * 128 + bc4;
    uint32_t abase = s2u(sm) + (ar * AP + ac) * 4;
    uint32_t bbase = s2u(sm) + (ASTF + br * BP + bc4) * 4;

    float acc[2][8][4];
    #pragma unroll
    for (int mt = 0; mt < 2; mt++)
        #pragma unroll
        for (int nt = 0; nt < 8; nt++)
            #pragma unroll
            for (int i = 0; i < 4; i++) acc[mt][nt][i] = 0.f;

    // prefetch stage 0
    {
        #pragma unroll
        for (int j = 0; j < 4; j++) cp16(abase + j * 16, asrc + j * 4);
        #pragma unroll
        for (int j = 0; j < 4; j++) cp16(bbase + j * 128, bsrc + j * 32);
        cp_commit();
    }

    for (int it = 0; it < 24; it++) {
        if (it < 23) {
            int st = (it + 1) & 1;
            const float* as2 = asrc + (it + 1) * 32;
            const float* bs2 = bsrc + (size_t)(it + 1) * 32 * N;
            uint32_t ad = abase + st * (STG * 4);
            uint32_t bd = bbase + st * (STG * 4);
            #pragma unroll
            for (int j = 0; j < 4; j++) cp16(ad + j * 16, as2 + j * 4);
            #pragma unroll
            for (int j = 0; j < 4; j++) cp16(bd + j * 128, bs2 + j * 32);
            cp_commit();
            asm volatile("cp.async.wait_group 1;" ::: "memory");
        } else {
            asm volatile("cp.async.wait_group 0;" ::: "memory");
        }
        __syncthreads();

        const float* As = sm + (it & 1) * STG;
        const float* Bs = As + ASTF;

        #pragma unroll
        for (int kk = 0; kk < 4; kk++) {
            int kr = kk * 8;
            uint32_t af[2][4], bf[8][2];
            #pragma unroll
            for (int mt = 0; mt < 2; mt++) {
                int r0 = (wm + mt * 16 + lg) * AP;
                af[mt][0] = fbits(As[r0            + kr + lq    ]);
                af[mt][1] = fbits(As[r0 + 8 * AP   + kr + lq    ]);
                af[mt][2] = fbits(As[r0            + kr + lq + 4]);
                af[mt][3] = fbits(As[r0 + 8 * AP   + kr + lq + 4]);
            }
            #pragma unroll
            for (int nt = 0; nt < 8; nt++) {
                bf[nt][0] = fbits(Bs[(kr + lq    ) * BP + wn + nt * 8 + lg]);
                bf[nt][1] = fbits(Bs[(kr + lq + 4) * BP + wn + nt * 8 + lg]);
            }
            #pragma unroll
            for (int mt = 0; mt < 2; mt++)
                #pragma unroll
                for (int nt = 0; nt < 8; nt++)
                    mma8(acc[mt][nt], af[mt], bf[nt]);
        }
        __syncthreads();
    }

    // Epilogue
    #pragma unroll
    for (int mt = 0; mt < 2; mt++) {
        #pragma unroll
        for (int rp = 0; rp < 2; rp++) {
            int m = by * 128 + wm + mt * 16 + lg + rp * 8;
            if (QKV) {
                int bb = m >> 11;
                int ss = m & (S_ - 1);
                #pragma unroll
                for (int nt = 0; nt < 8; nt++) {
                    int n = bx * 128 + wn + nt * 8 + 2 * lq;
                    int which = n / D_;
                    int rem = n - which * D_;
                    int hh = rem >> 6, dd = rem & 63;
                    float2 v;
                    v.x = tf32r(acc[mt][nt][rp*2 + 0] + bias[n]);
                    v.y = tf32r(acc[mt][nt][rp*2 + 1] + bias[n + 1]);
                    float* dst = (which == 0) ? g_q : ((which == 1) ? g_k : g_v);
                    *(float2*)&dst[(((size_t)(bb * H_ + hh) * S_ + ss) << 6) + dd] = v;
                }
            } else {
                #pragma unroll
                for (int nt = 0; nt < 8; nt++) {
                    int n = bx * 128 + wn + nt * 8 + 2 * lq;
                    float2 v;
                    v.x = acc[mt][nt][rp*2 + 0] + bias[n];
                    v.y = acc[mt][nt][rp*2 + 1] + bias[n + 1];
                    *(float2*)&C[(size_t)m * D_ + n] = v;
                }
            }
        }
    }
}

// ---------------------------------------------------------------------------
// Flash attention, causal, tf32 mma. One block = (b, h, 64-row q tile).
// 128 threads (4 warps), warp w owns q rows [w*16, w*16+16).
// SMEM: Ks[64][68], Vs[64][68], Ps[64][68] (Q staging then P). cp.async K/V.
// qt mapped descending so heavy blocks launch first.
// ---------------------------------------------------------------------------
__global__ __launch_bounds__(128) void flash_attn_tf32()
{
    extern __shared__ float sm[];
    float* Ks = sm;
    float* Vs = sm + 64 * 68;
    float* Ps = sm + 2 * 64 * 68;

    int bid = blockIdx.x;
    int qt = 31 - (bid & 31);          // descending work size
    int h  = (bid >> 5) % H_;
    int b  = bid / (32 * H_);
    int tid = threadIdx.x;
    int lane = tid & 31, w = tid >> 5, lg = lane >> 2, lq = lane & 3;
    int q0 = qt * 64;
    const float scale = 0.125f;        // exact power of 2, preserves tf32 pattern

    const float* Qg = g_q + (size_t)(b * H_ + h) * S_ * HD_;
    const float* Kg = g_k + (size_t)(b * H_ + h) * S_ * HD_;
    const float* Vg = g_v + (size_t)(b * H_ + h) * S_ * HD_;

    int r = tid >> 1, c0 = (tid & 1) * 32;
    uint32_t ks_u = s2u(Ks) + (r * 68 + c0) * 4;
    uint32_t vs_u = s2u(Vs) + (r * 68 + c0) * 4;
    const float* kg_row = Kg + (size_t)r * 64 + c0;
    const float* vg_row = Vg + (size_t)r * 64 + c0;

    // Stage Q tile (scaled; inputs pre-rounded, *0.125 exact) into Ps
    #pragma unroll
    for (int j = 0; j < 8; j++) {
        float4 q4 = *(const float4*)(Qg + (size_t)(q0 + r) * 64 + c0 + j * 4);
        q4.x *= scale; q4.y *= scale; q4.z *= scale; q4.w *= scale;
        *(float4*)&Ps[r * 68 + c0 + j * 4] = q4;
    }
    __syncthreads();

    uint32_t qf[8][4];
    #pragma unroll
    for (int kk = 0; kk < 8; kk++) {
        qf[kk][0] = fbits(Ps[(w*16 + lg    ) * 68 + kk*8 + lq    ]);
        qf[kk][1] = fbits(Ps[(w*16 + lg + 8) * 68 + kk*8 + lq    ]);
        qf[kk][2] = fbits(Ps[(w*16 + lg    ) * 68 + kk*8 + lq + 4]);
        qf[kk][3] = fbits(Ps[(w*16 + lg + 8) * 68 + kk*8 + lq + 4]);
    }
    __syncthreads();

    float mrow[2] = {-INFINITY, -INFINITY};
    float lrow[2] = {0.f, 0.f};
    float o[8][4];
    #pragma unroll
    for (int nt = 0; nt < 8; nt++)
        #pragma unroll
        for (int i = 0; i < 4; i++) o[nt][i] = 0.f;

    for (int kt = 0; kt <= qt; kt++) {
        size_t koff = (size_t)kt * 64 * 64;
        __syncthreads();   // prior reads of Ks/Vs done
        #pragma unroll
        for (int j = 0; j < 8; j++) cp16(ks_u + j * 16, kg_row + koff + j * 4);
        #pragma unroll
        for (int j = 0; j < 8; j++) cp16(vs_u + j * 16, vg_row + koff + j * 4);
        cp_commit();
        asm volatile("cp.async.wait_group 0;" ::: "memory");
        __syncthreads();

        // S = (Q*scale) @ K^T  — batched B-frag loads per kk for ILP
        float s[8][4];
        #pragma unroll
        for (int nt = 0; nt < 8; nt++)
            #pragma unroll
            for (int i = 0; i < 4; i++) s[nt][i] = 0.f;

        #pragma unroll
        for (int kk = 0; kk < 8; kk++) {
            uint32_t bv[8][2];
            #pragma unroll
            for (int nt = 0; nt < 8; nt++) {
                bv[nt][0] = fbits(Ks[(nt*8 + lg) * 68 + kk*8 + lq    ]);
                bv[nt][1] = fbits(Ks[(nt*8 + lg) * 68 + kk*8 + lq + 4]);
            }
            #pragma unroll
            for (int nt = 0; nt < 8; nt++)
                mma8(s[nt], qf[kk], bv[nt]);
        }

        if (kt == qt) {   // diagonal tile: causal mask
            #pragma unroll
            for (int nt = 0; nt < 8; nt++)
                #pragma unroll
                for (int rp = 0; rp < 2; rp++)
                    #pragma unroll
                    for (int j = 0; j < 2; j++) {
                        int col = nt*8 + 2*lq + j;
                        int row = w*16 + lg + rp*8;
                        if (col > row) s[nt][rp*2 + j] = -INFINITY;
                    }
        }

        // Online softmax (each thread owns rows lg, lg+8 of its warp tile)
        #pragma unroll
        for (int rp = 0; rp < 2; rp++) {
            float mt = -INFINITY;
            #pragma unroll
            for (int nt = 0; nt < 8; nt++)
                mt = fmaxf(mt, fmaxf(s[nt][rp*2], s[nt][rp*2 + 1]));
            mt = fmaxf(mt, __shfl_xor_sync(0xffffffffu, mt, 1));
            mt = fmaxf(mt, __shfl_xor_sync(0xffffffffu, mt, 2));
            float mnew = fmaxf(mrow[rp], mt);
            float alpha = __expf(mrow[rp] - mnew);
            float rs = 0.f;
            #pragma unroll
            for (int nt = 0; nt < 8; nt++) {
                float e0 = __expf(s[nt][rp*2]     - mnew);
                float e1 = __expf(s[nt][rp*2 + 1] - mnew);
                s[nt][rp*2] = e0; s[nt][rp*2 + 1] = e1;
                rs += e0 + e1;
            }
            rs += __shfl_xor_sync(0xffffffffu, rs, 1);
            rs += __shfl_xor_sync(0xffffffffu, rs, 2);
            lrow[rp] = lrow[rp] * alpha + rs;
            mrow[rp] = mnew;
            #pragma unroll
            for (int nt = 0; nt < 8; nt++) {
                o[nt][rp*2]     *= alpha;
                o[nt][rp*2 + 1] *= alpha;
            }
            #pragma unroll
            for (int nt = 0; nt < 8; nt++) {
                float2 pv;
                pv.x = tf32r(s[nt][rp*2]);
                pv.y = tf32r(s[nt][rp*2 + 1]);
                *(float2*)&Ps[(w*16 + lg + rp*8) * 68 + nt*8 + 2*lq] = pv;
            }
        }
        __syncwarp();

        // O += P @ V  — batched loads per kk
        #pragma unroll
        for (int kk = 0; kk < 8; kk++) {
            uint32_t pa[4];
            pa[0] = fbits(Ps[(w*16 + lg    ) * 68 + kk*8 + lq    ]);
            pa[1] = fbits(Ps[(w*16 + lg + 8) * 68 + kk*8 + lq    ]);
            pa[2] = fbits(Ps[(w*16 + lg    ) * 68 + kk*8 + lq + 4]);
            pa[3] = fbits(Ps[(w*16 + lg + 8) * 68 + kk*8 + lq + 4]);
            uint32_t bv[8][2];
            #pragma unroll
            for (int nt = 0; nt < 8; nt++) {
                bv[nt][0] = fbits(Vs[(kk*8 + lq    ) * 68 + nt*8 + lg]);
                bv[nt][1] = fbits(Vs[(kk*8 + lq + 4) * 68 + nt*8 + lg]);
            }
            #pragma unroll
            for (int nt = 0; nt < 8; nt++)
                mma8(o[nt], pa, bv[nt]);
        }
        __syncwarp();
    }

    // Normalize, tf32-round (proj A operand), write [b, s, h*64+d]
    #pragma unroll
    for (int rp = 0; rp < 2; rp++) {
        float inv = 1.f / lrow[rp];
        int row = q0 + w*16 + lg + rp*8;
        #pragma unroll
        for (int nt = 0; nt < 8; nt++) {
            int d = nt*8 + 2*lq;
            float2 v;
            v.x = tf32r(o[nt][rp*2]     * inv);
            v.y = tf32r(o[nt][rp*2 + 1] * inv);
            *(float2*)&g_attn[((size_t)(b * S_ + row)) * D_ + h * 64 + d] = v;
        }
    }
}

// ---------------------------------------------------------------------------
extern "C" void kernel_launch(void* const* d_in, const int* in_sizes, int n_in,
                              void* d_out, int out_size)
{
    const float* x      = (const float*)d_in[0];
    const float* b_qkv  = (const float*)d_in[2];
    const float* b_proj = (const float*)d_in[4];
    float* out = (float*)d_out;

    pre_round<<<dim3(256, 3), 256>>>(x, (const float*)d_in[1], (const float*)d_in[3]);

    int gsmem = 2 * STG * (int)sizeof(float);   // 71680 B
    cudaFuncSetAttribute(gemm_tf32<true>,
                         cudaFuncAttributeMaxDynamicSharedMemorySize, gsmem);
    cudaFuncSetAttribute(gemm_tf32<false>,
                         cudaFuncAttributeMaxDynamicSharedMemorySize, gsmem);

    dim3 g1(N3_ / 128, M_ / 128);   // (18, 64)
    gemm_tf32<true><<<g1, 256, gsmem>>>(b_qkv, nullptr, N3_);

    int asmem = 3 * 64 * 68 * (int)sizeof(float);   // 52224 B
    cudaFuncSetAttribute(flash_attn_tf32,
                         cudaFuncAttributeMaxDynamicSharedMemorySize, asmem);
    flash_attn_tf32<<<B_ * H_ * (S_ / 64), 128, asmem>>>();

    dim3 g2(D_ / 128, M_ / 128);    // (6, 64)
    gemm_tf32<false><<<g2, 256, gsmem>>>(b_proj, out, D_);
}